// round 9
// baseline (speedup 1.0000x reference)
#include <cuda_runtime.h>

#define B 64
#define H 768
#define E 128

#define KS 12                     // GEMM k-splits (K chunk = 64 floats)
#define NGEMM (KS * 8 * 2)        // 192 GEMM blocks, bids [0,192) — start first
#define NRED 256                  // reduce blocks, bids [192,448), 32 KB, MLP=8
#define GRID (NGEMM + NRED)       // 448; fits one wave (>=5 blk/SM by regs+smem)

__device__ float g_P[3][KS][E][B];     // [mat][ks][e][b] gemm partials (transposed)
__device__ unsigned g_arrive;          // gemm-arrive counter; self-resetting
__device__ unsigned g_done2;           // reduce-done counter; self-resetting

__global__ void __launch_bounds__(256)
k_all(const float* __restrict__ core,
      const float* __restrict__ hs, const float* __restrict__ rs,
      const float* __restrict__ ts, const float* __restrict__ we,
      const float* __restrict__ wr, const float* __restrict__ be,
      const float* __restrict__ br, float* __restrict__ out) {
    __shared__ float4 s_src[3][32][18];  // gemm src tiles (swizzled)
    __shared__ float4 s_w[2][16][18];    // gemm We/Wr tiles / reduce scratch

    const int bid = blockIdx.x;
    const int tid = threadIdx.x;

    if (bid < NGEMM) {
        // ------- triple GEMM (R2 proven): 32b x 16e x 64k tile --------------
        // Block 0 also zeroes out[] (safe: consumers read only after arrive).
        if (bid == 0 && tid < B) out[tid] = 0.f;

        const int ks = bid % KS, ec = (bid / KS) & 7, bg = bid / (KS * 8);
        const int b0 = bg * 32, e0 = ec * 16;
        const int c0 = ks * 16;  // float4 col offset (64-float K chunk)

        const float4* g0 = reinterpret_cast<const float4*>(hs);
        const float4* g1 = reinterpret_cast<const float4*>(rs);
        const float4* g2 = reinterpret_cast<const float4*>(ts);
#pragma unroll
        for (int i = tid; i < 512; i += 256) {
            const int row = i >> 4, c4 = i & 15;
            const size_t gidx = (size_t)(b0 + row) * 192 + c0 + c4;
            const int sc = c4 ^ (row & 7);
            s_src[0][row][sc] = g0[gidx];
            s_src[1][row][sc] = g1[gidx];
            s_src[2][row][sc] = g2[gidx];
        }
        {
            const int row = tid >> 4, c4 = tid & 15;
            const size_t gidx = (size_t)(e0 + row) * 192 + c0 + c4;
            const int sc = c4 ^ (row & 7);
            s_w[0][row][sc] = reinterpret_cast<const float4*>(we)[gidx];
            s_w[1][row][sc] = reinterpret_cast<const float4*>(wr)[gidx];
        }
        __syncthreads();

        const int te = tid & 15;   // e within tile
        const int tb = tid >> 4;   // b pair within tile
        const int ba = 2 * tb, bb = ba + 1;

        float h0 = 0.f, h1 = 0.f, r0 = 0.f, r1 = 0.f, t0 = 0.f, t1 = 0.f;
#pragma unroll
        for (int k4 = 0; k4 < 16; k4++) {
            const float4 vwe = s_w[0][te][k4 ^ (te & 7)];
            const float4 vwr = s_w[1][te][k4 ^ (te & 7)];
            const int sa = k4 ^ (ba & 7), sb = k4 ^ (bb & 7);
            float4 a, c;
            a = s_src[0][ba][sa]; c = s_src[0][bb][sb];
            h0 += vwe.x * a.x + vwe.y * a.y + vwe.z * a.z + vwe.w * a.w;
            h1 += vwe.x * c.x + vwe.y * c.y + vwe.z * c.z + vwe.w * c.w;
            a = s_src[1][ba][sa]; c = s_src[1][bb][sb];
            r0 += vwr.x * a.x + vwr.y * a.y + vwr.z * a.z + vwr.w * a.w;
            r1 += vwr.x * c.x + vwr.y * c.y + vwr.z * c.z + vwr.w * c.w;
            a = s_src[2][ba][sa]; c = s_src[2][bb][sb];
            t0 += vwe.x * a.x + vwe.y * a.y + vwe.z * a.z + vwe.w * a.w;
            t1 += vwe.x * c.x + vwe.y * c.y + vwe.z * c.z + vwe.w * c.w;
        }

        // transposed epilogue: [mat][ks][e][b]
        const int bga = b0 + ba, bgb = b0 + bb;
        const int eA = e0 + te;
        g_P[0][ks][eA][bga] = h0;  g_P[0][ks][eA][bgb] = h1;
        g_P[1][ks][eA][bga] = r0;  g_P[1][ks][eA][bgb] = r1;
        g_P[2][ks][eA][bga] = t0;  g_P[2][ks][eA][bgb] = t1;

        // release: make g_P (and block0's out zeros) visible, then arrive
        __threadfence();
        __syncthreads();
        if (tid == 0) atomicAdd(&g_arrive, 1u);
        return;                      // GEMM blocks never wait on anyone
    }

    // ------- core reduction: 32 KB chunk, 8 explicit loads (MLP=8) ---------
    const int rb = bid - NGEMM;
    const float4* src = reinterpret_cast<const float4*>(core) + (size_t)rb * 2048;
    const float4 v0 = __ldg(src + tid);
    const float4 v1 = __ldg(src + tid + 256);
    const float4 v2 = __ldg(src + tid + 512);
    const float4 v3 = __ldg(src + tid + 768);
    const float4 v4 = __ldg(src + tid + 1024);
    const float4 v5 = __ldg(src + tid + 1280);
    const float4 v6 = __ldg(src + tid + 1536);
    const float4 v7 = __ldg(src + tid + 1792);
    float s = ((((v0.x + v0.y) + (v0.z + v0.w)) + ((v1.x + v1.y) + (v1.z + v1.w)))
            +  (((v2.x + v2.y) + (v2.z + v2.w)) + ((v3.x + v3.y) + (v3.z + v3.w))))
            + ((((v4.x + v4.y) + (v4.z + v4.w)) + ((v5.x + v5.y) + (v5.z + v5.w)))
            +  (((v6.x + v6.y) + (v6.z + v6.w)) + ((v7.x + v7.y) + (v7.z + v7.w))));
#pragma unroll
    for (int o = 16; o > 0; o >>= 1) s += __shfl_xor_sync(0xffffffffu, s, o);
    float* ws = reinterpret_cast<float*>(s_w);
    if ((tid & 31) == 0) ws[tid >> 5] = s;
    __syncthreads();
    if (tid == 0) {
        float tot = 0.f;
#pragma unroll
        for (int w = 0; w < 8; w++) tot += ws[w];
        ws[8] = tot;                       // broadcast local S2 partial
        // acquire: wait for ALL GEMM blocks (fast, bid-first, co-resident)
        volatile unsigned* p = &g_arrive;
        while (*p < NGEMM) __nanosleep(32);
        __threadfence();
    }
    __syncthreads();

    // ------- fold: partial energy contribution for e = rb/2 ----------------
    // energy[b] -= (h+be)(r+br)(t+be) * s2_partial   (linear in s2 partials)
    const int e = rb >> 1;
    if (tid < B) {
        const float s2loc = ws[8];
        float h = 0.f, r = 0.f, t = 0.f;
#pragma unroll
        for (int k = 0; k < KS; k++) {
            h += g_P[0][k][e][tid];
            r += g_P[1][k][e][tid];
            t += g_P[2][k][e][tid];
        }
        const float v = (h + be[e]) * (r + br[e]) * (t + be[e]) * s2loc;
        atomicAdd(&out[tid], -v);
    }
    __syncthreads();

    if (tid == 0) {
        const unsigned d = atomicAdd(&g_done2, 1u);
        if (d == NRED - 1) {               // last reduce block resets counters
            g_arrive = 0u;
            __threadfence();
            g_done2 = 0u;
        }
    }
}

// ---------------------------------------------------------------------------
extern "C" void kernel_launch(void* const* d_in, const int* in_sizes, int n_in,
                              void* d_out, int out_size) {
    const float* head = (const float*)d_in[0];
    const float* rel  = (const float*)d_in[1];
    const float* tail = (const float*)d_in[2];
    const float* We   = (const float*)d_in[3];
    const float* be   = (const float*)d_in[4];
    const float* Wr   = (const float*)d_in[5];
    const float* br   = (const float*)d_in[6];
    const float* core = (const float*)d_in[7];
    float* out = (float*)d_out;

    k_all<<<GRID, 256>>>(core, head, rel, tail, We, Wr, be, br, out);
}

// round 10
// speedup vs baseline: 1.1351x; 1.1351x over previous
#include <cuda_runtime.h>

#define B 64
#define H 768
#define E 128

#define KS 12                      // GEMM k-splits (K chunk = 64 floats)
#define NGEMM 96                   // 12 ks x 4 echunk(32e) x 2 bgroup(32b)
#define NRED 256                   // reduce blocks, 32 KB each, MLP=8
#define GRID (NGEMM + NRED)        // 352; single wave (>=3 blk/SM regs, 4 smem)
#define NCOMB 64                   // combiners = last 64 blocks, 1 b-row each

__device__ float g_S2p[NRED];          // core partials (2 per leading index i)
__device__ float g_P[3][KS][B][E];     // [mat][ks][b][e] gemm partials
__device__ unsigned g_arrive;          // all-blocks arrive counter; self-reset
__device__ unsigned g_done2;           // combiner-done counter; self-reset

__global__ void __launch_bounds__(256, 3)
k_all(const float* __restrict__ core,
      const float* __restrict__ hs, const float* __restrict__ rs,
      const float* __restrict__ ts, const float* __restrict__ we,
      const float* __restrict__ wr, const float* __restrict__ be,
      const float* __restrict__ br, float* __restrict__ out) {
    __shared__ float4 s_src[3][32][18];  // gemm src tiles (swizzled)  27.6 KB
    __shared__ float4 s_w[2][32][18];    // gemm We/Wr tiles           18.4 KB

    const int bid = blockIdx.x;
    const int tid = threadIdx.x;

    if (bid < NGEMM) {
        // ------- triple GEMM: 32b x 32e x 64k tile, 2b x 2e per thread ------
        const int ks = bid % KS, ec = (bid / KS) & 3, bg = bid / (KS * 4);
        const int b0 = bg * 32, e0 = ec * 32;
        const int c0 = ks * 16;  // float4 col offset (64-float K chunk)

        const float4* g0 = reinterpret_cast<const float4*>(hs);
        const float4* g1 = reinterpret_cast<const float4*>(rs);
        const float4* g2 = reinterpret_cast<const float4*>(ts);
        const float4* gwe = reinterpret_cast<const float4*>(we);
        const float4* gwr = reinterpret_cast<const float4*>(wr);
#pragma unroll
        for (int i = tid; i < 512; i += 256) {
            const int row = i >> 4, c4 = i & 15;
            const size_t gidx = (size_t)(b0 + row) * 192 + c0 + c4;
            const int sc = c4 ^ (row & 7);
            s_src[0][row][sc] = g0[gidx];
            s_src[1][row][sc] = g1[gidx];
            s_src[2][row][sc] = g2[gidx];
        }
#pragma unroll
        for (int i = tid; i < 1024; i += 256) {
            const int m = i >> 9, row = (i >> 4) & 31, c4 = i & 15;
            const size_t gidx = (size_t)(e0 + row) * 192 + c0 + c4;
            const int sc = c4 ^ (row & 7);
            s_w[m][row][sc] = m ? gwr[gidx] : gwe[gidx];
        }
        __syncthreads();

        const int te = tid & 15;   // e pair: (e0+te, e0+te+16)
        const int tb = tid >> 4;   // b pair: (b0+2tb, b0+2tb+1)
        const int ba = 2 * tb, bb = ba + 1;

        float h00 = 0.f, h01 = 0.f, h10 = 0.f, h11 = 0.f;
        float r00 = 0.f, r01 = 0.f, r10 = 0.f, r11 = 0.f;
        float t00 = 0.f, t01 = 0.f, t10 = 0.f, t11 = 0.f;
#pragma unroll
        for (int k4 = 0; k4 < 16; k4++) {
            const int sw = k4 ^ (te & 7);
            const float4 weA = s_w[0][te][sw];
            const float4 weB = s_w[0][te + 16][sw];
            const float4 wrA = s_w[1][te][sw];
            const float4 wrB = s_w[1][te + 16][sw];
            const int sa = k4 ^ (ba & 7), sb = k4 ^ (bb & 7);
            const float4 ah0 = s_src[0][ba][sa], ah1 = s_src[0][bb][sb];
            const float4 ar0 = s_src[1][ba][sa], ar1 = s_src[1][bb][sb];
            const float4 at0 = s_src[2][ba][sa], at1 = s_src[2][bb][sb];

            h00 += weA.x * ah0.x + weA.y * ah0.y + weA.z * ah0.z + weA.w * ah0.w;
            h01 += weB.x * ah0.x + weB.y * ah0.y + weB.z * ah0.z + weB.w * ah0.w;
            h10 += weA.x * ah1.x + weA.y * ah1.y + weA.z * ah1.z + weA.w * ah1.w;
            h11 += weB.x * ah1.x + weB.y * ah1.y + weB.z * ah1.z + weB.w * ah1.w;
            r00 += wrA.x * ar0.x + wrA.y * ar0.y + wrA.z * ar0.z + wrA.w * ar0.w;
            r01 += wrB.x * ar0.x + wrB.y * ar0.y + wrB.z * ar0.z + wrB.w * ar0.w;
            r10 += wrA.x * ar1.x + wrA.y * ar1.y + wrA.z * ar1.z + wrA.w * ar1.w;
            r11 += wrB.x * ar1.x + wrB.y * ar1.y + wrB.z * ar1.z + wrB.w * ar1.w;
            t00 += weA.x * at0.x + weA.y * at0.y + weA.z * at0.z + weA.w * at0.w;
            t01 += weB.x * at0.x + weB.y * at0.y + weB.z * at0.z + weB.w * at0.w;
            t10 += weA.x * at1.x + weA.y * at1.y + weA.z * at1.z + weA.w * at1.w;
            t11 += weB.x * at1.x + weB.y * at1.y + weB.z * at1.z + weB.w * at1.w;
        }

        const int bA = b0 + ba, bB = b0 + bb;
        const int eA = e0 + te, eB = e0 + te + 16;
        g_P[0][ks][bA][eA] = h00;  g_P[0][ks][bA][eB] = h01;
        g_P[0][ks][bB][eA] = h10;  g_P[0][ks][bB][eB] = h11;
        g_P[1][ks][bA][eA] = r00;  g_P[1][ks][bA][eB] = r01;
        g_P[1][ks][bB][eA] = r10;  g_P[1][ks][bB][eB] = r11;
        g_P[2][ks][bA][eA] = t00;  g_P[2][ks][bA][eB] = t01;
        g_P[2][ks][bB][eA] = t10;  g_P[2][ks][bB][eB] = t11;

        __threadfence();
        __syncthreads();
        if (tid == 0) atomicAdd(&g_arrive, 1u);
        return;                         // GEMM blocks never wait
    }

    // ------- core reduction: 32 KB chunk, 8 explicit loads (MLP=8) ---------
    const int rb = bid - NGEMM;
    {
        const float4* src = reinterpret_cast<const float4*>(core) + (size_t)rb * 2048;
        const float4 v0 = __ldg(src + tid);
        const float4 v1 = __ldg(src + tid + 256);
        const float4 v2 = __ldg(src + tid + 512);
        const float4 v3 = __ldg(src + tid + 768);
        const float4 v4 = __ldg(src + tid + 1024);
        const float4 v5 = __ldg(src + tid + 1280);
        const float4 v6 = __ldg(src + tid + 1536);
        const float4 v7 = __ldg(src + tid + 1792);
        float s = ((((v0.x + v0.y) + (v0.z + v0.w)) + ((v1.x + v1.y) + (v1.z + v1.w)))
                +  (((v2.x + v2.y) + (v2.z + v2.w)) + ((v3.x + v3.y) + (v3.z + v3.w))))
                + ((((v4.x + v4.y) + (v4.z + v4.w)) + ((v5.x + v5.y) + (v5.z + v5.w)))
                +  (((v6.x + v6.y) + (v6.z + v6.w)) + ((v7.x + v7.y) + (v7.z + v7.w))));
#pragma unroll
        for (int o = 16; o > 0; o >>= 1) s += __shfl_xor_sync(0xffffffffu, s, o);
        float* ws = reinterpret_cast<float*>(s_w);
        if ((tid & 31) == 0) ws[tid >> 5] = s;
        __syncthreads();
        if (tid == 0) {
            float tot = 0.f;
#pragma unroll
            for (int w = 0; w < 8; w++) tot += ws[w];
            g_S2p[rb] = tot;
            __threadfence();
            atomicAdd(&g_arrive, 1u);
        }
    }

    if (bid < GRID - NCOMB) return;

    // ------- combine (last 64 blocks): one batch row b each, ONE pass -------
    if (tid == 0) {
        volatile unsigned* p = &g_arrive;
        while (*p < GRID) __nanosleep(16);
    }
    __syncthreads();
    __threadfence();

    const int b = bid - (GRID - NCOMB);           // 0..63
    float* sx = reinterpret_cast<float*>(s_src);  // scratch
    const int e = tid & 127;
    const int half = tid >> 7;                    // ks half: 0 -> 0..5, 1 -> 6..11
    const int k0 = half * 6;

    float h = 0.f, r = 0.f, t = 0.f;
#pragma unroll
    for (int k = 0; k < 6; k++) {                 // 18 independent coalesced loads
        h += g_P[0][k0 + k][b][e];
        r += g_P[1][k0 + k][b][e];
        t += g_P[2][k0 + k][b][e];
    }
    if (half == 1) { sx[e] = h; sx[128 + e] = r; sx[256 + e] = t; }
    __syncthreads();
    if (half == 0) {
        h += sx[e]; r += sx[128 + e]; t += sx[256 + e];
        const float s2 = g_S2p[2 * e] + g_S2p[2 * e + 1];
        float v = (h + be[e]) * (r + br[e]) * (t + be[e]) * s2;
#pragma unroll
        for (int o = 16; o > 0; o >>= 1) v += __shfl_xor_sync(0xffffffffu, v, o);
        if ((e & 31) == 0) sx[384 + (e >> 5)] = v;
    }
    __syncthreads();
    if (tid == 0)
        out[b] = -((sx[384] + sx[385]) + (sx[386] + sx[387]));

    if (tid == 0) {
        const unsigned d = atomicAdd(&g_done2, 1u);
        if (d == NCOMB - 1) {            // last combiner resets for next replay
            g_arrive = 0u;
            __threadfence();
            g_done2 = 0u;
        }
    }
}

// ---------------------------------------------------------------------------
extern "C" void kernel_launch(void* const* d_in, const int* in_sizes, int n_in,
                              void* d_out, int out_size) {
    const float* head = (const float*)d_in[0];
    const float* rel  = (const float*)d_in[1];
    const float* tail = (const float*)d_in[2];
    const float* We   = (const float*)d_in[3];
    const float* be   = (const float*)d_in[4];
    const float* Wr   = (const float*)d_in[5];
    const float* br   = (const float*)d_in[6];
    const float* core = (const float*)d_in[7];
    float* out = (float*)d_out;

    k_all<<<GRID, 256>>>(core, head, rel, tail, We, Wr, be, br, out);
}

// round 11
// speedup vs baseline: 1.3791x; 1.2149x over previous
#include <cuda_runtime.h>

#define B 64
#define H 768
#define E 128

#define NRED 256    // core-reduce blocks (32 KB each), bids [0,256)
#define KS 12       // GEMM k-splits
#define NGEMM 192   // 12 ks x 8 echunk x 2 bgroup, bids [256,448)
#define GRID (NRED + NGEMM)

__device__ float g_S2p[NRED];          // core partials (2 per leading index i)
__device__ float g_P[3][KS][B][E];     // [mat][ks][b][e] gemm partials

// ---------------------------------------------------------------------------
// Kernel A (R2-proven, unchanged): blocks [0,256) reduce core (MLP=8);
// blocks [256,448) triple GEMM 32b x 16e x 64k.
// ---------------------------------------------------------------------------
__global__ void k_fused(const float* __restrict__ core,
                        const float* __restrict__ hs, const float* __restrict__ rs,
                        const float* __restrict__ ts, const float* __restrict__ we,
                        const float* __restrict__ wr) {
    __shared__ float4 s_src[3][32][18];  // gemm src tiles (swizzled)
    __shared__ float4 s_w[2][16][18];    // gemm We/Wr tiles

    const int bid = blockIdx.x;
    const int tid = threadIdx.x;

    if (bid < NRED) {
        const float4* src = reinterpret_cast<const float4*>(core) + (size_t)bid * 2048;
        const float4 v0 = __ldg(src + tid);
        const float4 v1 = __ldg(src + tid + 256);
        const float4 v2 = __ldg(src + tid + 512);
        const float4 v3 = __ldg(src + tid + 768);
        const float4 v4 = __ldg(src + tid + 1024);
        const float4 v5 = __ldg(src + tid + 1280);
        const float4 v6 = __ldg(src + tid + 1536);
        const float4 v7 = __ldg(src + tid + 1792);
        float s = ((((v0.x + v0.y) + (v0.z + v0.w)) + ((v1.x + v1.y) + (v1.z + v1.w)))
                +  (((v2.x + v2.y) + (v2.z + v2.w)) + ((v3.x + v3.y) + (v3.z + v3.w))))
                + ((((v4.x + v4.y) + (v4.z + v4.w)) + ((v5.x + v5.y) + (v5.z + v5.w)))
                +  (((v6.x + v6.y) + (v6.z + v6.w)) + ((v7.x + v7.y) + (v7.z + v7.w))));
#pragma unroll
        for (int o = 16; o > 0; o >>= 1) s += __shfl_xor_sync(0xffffffffu, s, o);
        float* ws = reinterpret_cast<float*>(s_w);
        if ((tid & 31) == 0) ws[tid >> 5] = s;
        __syncthreads();
        if (tid == 0) {
            float tot = 0.f;
#pragma unroll
            for (int w = 0; w < 8; w++) tot += ws[w];
            g_S2p[bid] = tot;
        }
        return;
    }

    const int lin = bid - NRED;
    const int ks = lin % KS, ec = (lin / KS) & 7, bg = lin / (KS * 8);
    const int b0 = bg * 32, e0 = ec * 16;
    const int c0 = ks * 16;

    const float4* g0 = reinterpret_cast<const float4*>(hs);
    const float4* g1 = reinterpret_cast<const float4*>(rs);
    const float4* g2 = reinterpret_cast<const float4*>(ts);
#pragma unroll
    for (int i = tid; i < 512; i += 256) {
        const int row = i >> 4, c4 = i & 15;
        const size_t gidx = (size_t)(b0 + row) * 192 + c0 + c4;
        const int sc = c4 ^ (row & 7);
        s_src[0][row][sc] = g0[gidx];
        s_src[1][row][sc] = g1[gidx];
        s_src[2][row][sc] = g2[gidx];
    }
    {
        const int row = tid >> 4, c4 = tid & 15;
        const size_t gidx = (size_t)(e0 + row) * 192 + c0 + c4;
        const int sc = c4 ^ (row & 7);
        s_w[0][row][sc] = reinterpret_cast<const float4*>(we)[gidx];
        s_w[1][row][sc] = reinterpret_cast<const float4*>(wr)[gidx];
    }
    __syncthreads();

    const int te = tid & 15;
    const int tb = tid >> 4;
    const int ba = 2 * tb, bb = ba + 1;

    float h0 = 0.f, h1 = 0.f, r0 = 0.f, r1 = 0.f, t0 = 0.f, t1 = 0.f;
#pragma unroll
    for (int k4 = 0; k4 < 16; k4++) {
        const float4 vwe = s_w[0][te][k4 ^ (te & 7)];
        const float4 vwr = s_w[1][te][k4 ^ (te & 7)];
        const int sa = k4 ^ (ba & 7), sb = k4 ^ (bb & 7);
        float4 a, c;
        a = s_src[0][ba][sa]; c = s_src[0][bb][sb];
        h0 += vwe.x * a.x + vwe.y * a.y + vwe.z * a.z + vwe.w * a.w;
        h1 += vwe.x * c.x + vwe.y * c.y + vwe.z * c.z + vwe.w * c.w;
        a = s_src[1][ba][sa]; c = s_src[1][bb][sb];
        r0 += vwr.x * a.x + vwr.y * a.y + vwr.z * a.z + vwr.w * a.w;
        r1 += vwr.x * c.x + vwr.y * c.y + vwr.z * c.z + vwr.w * c.w;
        a = s_src[2][ba][sa]; c = s_src[2][bb][sb];
        t0 += vwe.x * a.x + vwe.y * a.y + vwe.z * a.z + vwe.w * a.w;
        t1 += vwe.x * c.x + vwe.y * c.y + vwe.z * c.z + vwe.w * c.w;
    }

    const int bga = b0 + ba, bgb = b0 + bb;
    const int e = e0 + te;
    g_P[0][ks][bga][e] = h0;  g_P[0][ks][bgb][e] = h1;
    g_P[1][ks][bga][e] = r0;  g_P[1][ks][bgb][e] = r1;
    g_P[2][ks][bga][e] = t0;  g_P[2][ks][bgb][e] = t1;
}

// ---------------------------------------------------------------------------
// Kernel B (rewritten): 64 blocks x 384 threads. Thread (m,e) sums 12 ks
// partials (12 independent coalesced L2 loads -> MLP=12), smem exchange,
// then 128 threads do the triple product + block reduce.
// ---------------------------------------------------------------------------
__global__ void k_combine(const float* __restrict__ be, const float* __restrict__ br,
                          float* __restrict__ out) {
    __shared__ float sh[3][128];
    __shared__ float sred[4];

    const int b = blockIdx.x;
    const int tid = threadIdx.x;           // 0..383
    const int m = tid >> 7;                // matrix 0/1/2
    const int e = tid & 127;

    const float* p = &g_P[m][0][b][e];     // stride between ks = B*E floats
    float s = 0.f;
#pragma unroll
    for (int k = 0; k < KS; k++) s += __ldg(p + (size_t)k * (B * E));
    sh[m][e] = s;
    __syncthreads();

    if (tid < 128) {
        const float bias_e = be[tid], bias_r = br[tid];
        const float h = sh[0][tid] + bias_e;
        const float r = sh[1][tid] + bias_r;
        const float t = sh[2][tid] + bias_e;
        const float s2 = g_S2p[2 * tid] + g_S2p[2 * tid + 1];
        float v = h * r * t * s2;
#pragma unroll
        for (int o = 16; o > 0; o >>= 1) v += __shfl_xor_sync(0xffffffffu, v, o);
        if ((tid & 31) == 0) sred[tid >> 5] = v;
    }
    __syncthreads();
    if (tid == 0) out[b] = -((sred[0] + sred[1]) + (sred[2] + sred[3]));
}

// ---------------------------------------------------------------------------
extern "C" void kernel_launch(void* const* d_in, const int* in_sizes, int n_in,
                              void* d_out, int out_size) {
    const float* head = (const float*)d_in[0];
    const float* rel  = (const float*)d_in[1];
    const float* tail = (const float*)d_in[2];
    const float* We   = (const float*)d_in[3];
    const float* be   = (const float*)d_in[4];
    const float* Wr   = (const float*)d_in[5];
    const float* br   = (const float*)d_in[6];
    const float* core = (const float*)d_in[7];
    float* out = (float*)d_out;

    k_fused<<<GRID, 256>>>(core, head, rel, tail, We, Wr);
    k_combine<<<B, 384>>>(be, br, out);
}